// round 12
// baseline (speedup 1.0000x reference)
#include <cuda_runtime.h>
#include <cuda_fp16.h>
#include <cstdint>

// Problem constants
#define BB 16
#define NN 4096
#define MM 1024
#define KK 32
#define FF 128

// out[b,m,f] = max_k inputs[b, idx[b,m,k], f]
//
// R10 lesson: SMEM-cached gather works (compulsory DRAM only) but 1 block/SM
// (144 KB smem) + reg-starved scheduling left it latency-bound (occ 24.5%).
// R11: FT=8 slice -> 80 KB smem -> 2 blocks/SM (32 warps), 256 blocks,
// 8 rows per warp-LDS.32, 2-way row interleave for independent chains.

#define FT       8                   // halfs per feature tile
#define RS       5                   // half2 per smem row (4 data + 1 pad; odd -> uniform bank spread)
#define THREADS  512
#define SMEMB    (NN * RS * 4)       // 4096*5*4 = 81920 B

__global__ __launch_bounds__(THREADS, 2) void gmp_kernel(
    const float* __restrict__ inputs,
    const int*   __restrict__ batch_index,
    float*       __restrict__ out)
{
    extern __shared__ __half2 stab[];          // [NN * RS]

    const int bid  = blockIdx.x;
    const int b    = bid >> 4;                 // batch (256 blocks = 16 x 16)
    const int ft   = bid & 15;                 // feature tile (8 halfs)
    const int tid  = threadIdx.x;
    const int lane = tid & 31;
    const int w    = tid >> 5;
    const int c    = lane & 3;                 // half2 col within tile (0..3)
    const int g    = lane >> 2;                // group (row slot) 0..7

    // ---- Phase 1: load + convert this block's [NN, FT] slice into SMEM ----
    {
        // Row n: 8 floats = 2 float4 at inputs[b][n][ft*8 ..]. 16B-aligned (ft*8 floats = 32B).
        const float4* src = (const float4*)(inputs + (size_t)b * (NN * FF) + ft * FT);
        #pragma unroll
        for (int i = 0; i < (NN * 2) / THREADS; ++i) {   // 16 iterations
            const int s  = tid + i * THREADS;
            const int n  = s >> 1;
            const int cc = s & 1;                        // which float4 (0..1)
            const float4 f = __ldg(&src[(size_t)n * (FF / 4) + cc]);
            stab[n * RS + cc * 2 + 0] = __floats2half2_rn(f.x, f.y);
            stab[n * RS + cc * 2 + 1] = __floats2half2_rn(f.z, f.w);
        }
    }
    __syncthreads();

    const __half2 NEGH = __floats2half2_rn(-3.402823466e+38f, -3.402823466e+38f);
    const int* idxb = batch_index + (size_t)b * (MM * KK);

    // Component picker: compile-time after unroll (k&7 selects among 8 idx ints).
    #define PICK(A0, A1, KK7, V)  do {                 \
        switch (KK7) {                                 \
            case 0: V = (A0).x; break;                 \
            case 1: V = (A0).y; break;                 \
            case 2: V = (A0).z; break;                 \
            case 3: V = (A0).w; break;                 \
            case 4: V = (A1).x; break;                 \
            case 5: V = (A1).y; break;                 \
            case 6: V = (A1).z; break;                 \
            default: V = (A1).w; break;                \
        } } while (0)

    // ---- Phase 2: gather-max from SMEM. 16 rows/warp/iter (2 sets of 8). ----
    #pragma unroll 1
    for (int iter = 0; iter < MM / 256; ++iter) {      // 4 iterations
        const int m0 = iter * 256 + w * 16 + g;        // set A row
        const int m1 = m0 + 8;                         // set B row

        // Lane c holds indices k = 8c..8c+7 of its group's row (2 x int4).
        // Per row: 4 lanes x 32B = 128B contiguous; 8 consecutive rows per warp.
        const int4* p0 = (const int4*)(idxb + (size_t)m0 * KK);
        const int4* p1 = (const int4*)(idxb + (size_t)m1 * KK);
        int4 a0 = __ldg(p0 + c * 2);
        int4 a1 = __ldg(p0 + c * 2 + 1);
        int4 b0 = __ldg(p1 + c * 2);
        int4 b1 = __ldg(p1 + c * 2 + 1);
        // Mask to [0, NN): identity on valid data, OOB-proof.
        a0.x &= NN - 1; a0.y &= NN - 1; a0.z &= NN - 1; a0.w &= NN - 1;
        a1.x &= NN - 1; a1.y &= NN - 1; a1.z &= NN - 1; a1.w &= NN - 1;
        b0.x &= NN - 1; b0.y &= NN - 1; b0.z &= NN - 1; b0.w &= NN - 1;
        b1.x &= NN - 1; b1.y &= NN - 1; b1.z &= NN - 1; b1.w &= NN - 1;

        __half2 acc0 = NEGH, acc1 = NEGH;
        #pragma unroll
        for (int k = 0; k < KK; ++k) {
            int v0, v1;
            PICK(a0, a1, k & 7, v0);
            PICK(b0, b1, k & 7, v1);
            // Broadcast within 4-lane group: source lane k>>3 (0..3).
            const int t0 = __shfl_sync(0xffffffffu, v0, k >> 3, 4);
            const int t1 = __shfl_sync(0xffffffffu, v1, k >> 3, 4);
            // Two independent LDS.32 chains; banks (5t + c) mod 32.
            acc0 = __hmax2(acc0, stab[t0 * RS + c]);
            acc1 = __hmax2(acc1, stab[t1 * RS + c]);
        }

        // Store: lane writes 2 floats of its row; 4 lanes x 8B = 32B/row.
        const float2 f0 = __half22float2(acc0);
        const float2 f1 = __half22float2(acc1);
        float2* o0 = (float2*)(out + (size_t)b * (MM * FF) + (size_t)m0 * FF + ft * FT);
        float2* o1 = (float2*)(out + (size_t)b * (MM * FF) + (size_t)m1 * FF + ft * FT);
        __stcs(&o0[c], f0);
        __stcs(&o1[c], f1);
    }
    #undef PICK
}

extern "C" void kernel_launch(void* const* d_in, const int* in_sizes, int n_in,
                              void* d_out, int out_size)
{
    // Identify inputs by element count:
    //   inputs:      16*4096*128 = 8388608 (f32)
    //   batch_index: 16*1024*32  =  524288 (i32)
    const float* inputs;
    const int*   batch_index;
    if (in_sizes[0] == BB * NN * FF) {
        inputs      = (const float*)d_in[0];
        batch_index = (const int*)d_in[1];
    } else {
        inputs      = (const float*)d_in[1];
        batch_index = (const int*)d_in[0];
    }
    float* out = (float*)d_out;

    // 81920 B dynamic smem > 48KB default: opt in (host-side, idempotent).
    cudaFuncSetAttribute(gmp_kernel,
                         cudaFuncAttributeMaxDynamicSharedMemorySize, SMEMB);

    // One block per (batch, 8-half feature tile): 16 * 16 = 256 blocks.
    gmp_kernel<<<BB * (FF / FT), THREADS, SMEMB>>>(inputs, batch_index, out);
}

// round 13
// speedup vs baseline: 1.4531x; 1.4531x over previous
#include <cuda_runtime.h>
#include <cuda_fp16.h>
#include <cstdint>

// Problem constants
#define BB 16
#define NN 4096
#define MM 1024
#define KK 32
#define FF 128

// out[b,m,f] = max_k inputs[b, idx[b,m,k], f]
//
// R10/R11 lesson: SMEM caching kills the 128 MB L2 gather amplification, but
// partial-row tiles caused ~3.5x bank conflicts + latency serialization.
// R12: FT=16-half slices, 32B ALIGNED rows, lane-PAIR LDS.128 per gathered
// row -> aligned 8-bank spans (conflict ~1.6x), 16 gathers per LDS.128.
// One block per (batch, tile): 128 blocks x 1024 threads, 128 KB smem,
// fp32->fp16 conversion fused into phase 1 (no separate convert kernel).

#define FT       16                  // halfs per feature tile
#define THREADS  1024
#define SMEMB    (NN * FT * 2)       // 4096 rows * 32 B = 131072 B

__global__ __launch_bounds__(THREADS, 1) void gmp_kernel(
    const float* __restrict__ inputs,
    const int*   __restrict__ batch_index,
    float*       __restrict__ out)
{
    extern __shared__ uint2 stab2[];           // [NN*4] : row n = stab2[n*4 .. n*4+3]

    const int bid  = blockIdx.x;
    const int b    = bid >> 3;                 // batch (128 blocks = 16 x 8)
    const int ft   = bid & 7;                  // feature tile (16 halfs)
    const int tid  = threadIdx.x;
    const int lane = tid & 31;
    const int w    = tid >> 5;
    const int half = lane & 1;                 // which 8-half slice of the row
    const int pr   = lane >> 1;                // pair id 0..15 (row slot)

    // ---- Phase 1: load + convert [NN, 16] fp32 slice -> fp16 smem ----
    {
        // Thread task s: row n = s>>2, float4 cc = s&3 (16 floats per row).
        const float4* src = (const float4*)(inputs + (size_t)b * (NN * FF) + ft * FT);
        #pragma unroll
        for (int i = 0; i < (NN * 4) / THREADS; ++i) {   // 16 iterations
            const int s  = tid + i * THREADS;
            const int n  = s >> 2;
            const int cc = s & 3;
            const float4 f = __ldg(&src[(size_t)n * (FF / 4) + cc]);
            uint2 v;
            __half2 h0 = __floats2half2_rn(f.x, f.y);
            __half2 h1 = __floats2half2_rn(f.z, f.w);
            v.x = *reinterpret_cast<unsigned*>(&h0);
            v.y = *reinterpret_cast<unsigned*>(&h1);
            stab2[n * 4 + cc] = v;             // 8B store, row = 32B aligned
        }
    }
    __syncthreads();

    const uint4* __restrict__ stab4 = (const uint4*)stab2;  // row n = stab4[2n], stab4[2n+1]
    const __half2 NEGH = __floats2half2_rn(-3.402823466e+38f, -3.402823466e+38f);
    const int* idxb = batch_index + (size_t)b * (MM * KK);

    #define U2H(u) (*reinterpret_cast<const __half2*>(&(u)))
    // Pick int #sel (0..3) of an int4 — compile-time after unroll.
    #define PICK4(A, SEL, V) do {                    \
        switch (SEL) {                               \
            case 0: V = (A).x; break;                \
            case 1: V = (A).y; break;                \
            case 2: V = (A).z; break;                \
            default: V = (A).w; break;               \
        } } while (0)

    // ---- Phase 2: gather-max. Warp handles 16 rows/iter (lane pair = row). --
    #pragma unroll 1
    for (int iter = 0; iter < MM / (32 * 16); ++iter) {    // 2 iterations
        const int m = (iter * 32 + w) * 16 + pr;           // this pair's row

        // Row m's 32 indices = 128B. Even lane holds k=0..15 (4 int4),
        // odd lane holds k=16..31.
        const int4* ip = (const int4*)(idxb + (size_t)m * KK) + half * 4;
        const int4 a0 = __ldg(ip + 0);
        const int4 a1 = __ldg(ip + 1);
        const int4 a2 = __ldg(ip + 2);
        const int4 a3 = __ldg(ip + 3);

        __half2 c0 = NEGH, c1 = NEGH, c2 = NEGH, c3 = NEGH;

        #pragma unroll
        for (int k = 0; k < KK; ++k) {
            // Source: pair-lane k>>4, int4 (k&15)>>2, component k&3.
            int v;
            switch ((k & 15) >> 2) {
                case 0: PICK4(a0, k & 3, v); break;
                case 1: PICK4(a1, k & 3, v); break;
                case 2: PICK4(a2, k & 3, v); break;
                default: PICK4(a3, k & 3, v); break;
            }
            const int t = __shfl_sync(0xffffffffu, v, k >> 4, 2) & (NN - 1);
            // LDS.128: lane reads its 16B half of row t (32B aligned span).
            const uint4 r = stab4[t * 2 + half];
            c0 = __hmax2(c0, U2H(r.x));
            c1 = __hmax2(c1, U2H(r.y));
            c2 = __hmax2(c2, U2H(r.z));
            c3 = __hmax2(c3, U2H(r.w));
        }

        // Lane owns 8 consecutive features of row m -> two float4 stores.
        const float2 f0 = __half22float2(c0);
        const float2 f1 = __half22float2(c1);
        const float2 f2 = __half22float2(c2);
        const float2 f3 = __half22float2(c3);
        float4* orow = (float4*)(out + (size_t)b * (MM * FF) + (size_t)m * FF
                                 + ft * FT + half * 8);
        float4 o0; o0.x = f0.x; o0.y = f0.y; o0.z = f1.x; o0.w = f1.y;
        float4 o1; o1.x = f2.x; o1.y = f2.y; o1.z = f3.x; o1.w = f3.y;
        __stcs(&orow[0], o0);
        __stcs(&orow[1], o1);
    }
    #undef PICK4
    #undef U2H
}

extern "C" void kernel_launch(void* const* d_in, const int* in_sizes, int n_in,
                              void* d_out, int out_size)
{
    // Identify inputs by element count:
    //   inputs:      16*4096*128 = 8388608 (f32)
    //   batch_index: 16*1024*32  =  524288 (i32)
    const float* inputs;
    const int*   batch_index;
    if (in_sizes[0] == BB * NN * FF) {
        inputs      = (const float*)d_in[0];
        batch_index = (const int*)d_in[1];
    } else {
        inputs      = (const float*)d_in[1];
        batch_index = (const int*)d_in[0];
    }
    float* out = (float*)d_out;

    // 131072 B dynamic smem > 48KB default: opt in (host-side, idempotent).
    cudaFuncSetAttribute(gmp_kernel,
                         cudaFuncAttributeMaxDynamicSharedMemorySize, SMEMB);

    // One block per (batch, 16-half feature tile): 16 * 8 = 128 blocks.
    gmp_kernel<<<BB * (FF / FT), THREADS, SMEMB>>>(inputs, batch_index, out);
}